// round 12
// baseline (speedup 1.0000x reference)
#include <cuda_runtime.h>
#include <cuda_fp16.h>
#include <cstdint>

#define BATCH 32
#define LLEN  2048
#define BL    (BATCH * LLEN)      // 65536
#define NCTS  16                  // 4 ntiles x 4 warp columns

// ------------------------------- device scratch ----------------------------
__device__ __align__(16) __half g_h_hi[67108864];   // [BL][1024] fp16(h)
__device__ __align__(16) __half g_w_hi[1048576];    // [1024 N][1024 K] fp16(W)
__device__ float g_bias[1024];
__device__ float g_spart[NCTS * BL];
__device__ float g_a[BL];
__device__ float g_rpart[8][BATCH * 1024];

// ------------------------------- PTX helpers -------------------------------
__device__ __forceinline__ uint32_t smem_u32(const void* p) {
    uint32_t a;
    asm("{ .reg .u64 t; cvta.to.shared.u64 t, %1; cvt.u32.u64 %0, t; }" : "=r"(a) : "l"(p));
    return a;
}
__device__ __forceinline__ void cp16(uint32_t dst, const void* src) {
    asm volatile("cp.async.cg.shared.global [%0], [%1], 16;" :: "r"(dst), "l"(src));
}
#define LDSM4(r, addr) \
    asm volatile("ldmatrix.sync.aligned.m8n8.x4.shared.b16 {%0,%1,%2,%3}, [%4];" \
        : "=r"((r)[0]), "=r"((r)[1]), "=r"((r)[2]), "=r"((r)[3]) : "r"(addr))

__device__ __forceinline__ void mma16816h(float* d, const uint32_t* a,
                                          uint32_t b0, uint32_t b1) {
    asm volatile("mma.sync.aligned.m16n8k16.row.col.f32.f16.f16.f32 "
        "{%0,%1,%2,%3}, {%4,%5,%6,%7}, {%8,%9}, {%0,%1,%2,%3};"
        : "+f"(d[0]), "+f"(d[1]), "+f"(d[2]), "+f"(d[3])
        : "r"(a[0]), "r"(a[1]), "r"(a[2]), "r"(a[3]), "r"(b0), "r"(b1));
}

__device__ __forceinline__ float tanh_fast(float x) {
    float e = __expf(2.f * x);
    return 1.f - 2.f / (e + 1.f);
}

// ------------------------------- GEMM constants ----------------------------
// CTA tile 128(M) x 256(N). Per stage (48 KB): A 16K (128 rows x 128 B) |
// B 32K (256 rows x 128 B), SW128. 3 stages = 144 KB + 2 KB params,
// 1 CTA/SM (register-bound anyway).
#define STAGE_STRIDE 49152
#define OFF_A 0
#define OFF_B 16384
#define OFF_SBIAS 147456
#define OFF_SVW   148480
#define SMEM_BYTES 149504

// ---------------------------------------------------------------------------
// HMMA GEMM: pre[128 rows, 256 cols] over K=1024, fp16 x fp16 -> fp32.
// 8 warps in 2M x 4N grid, warp tile 64x64. Crossbar traffic per chunk
// (176 KB ~ 1375 cyc) now BELOW MMA pipe time (2048 cyc) — tensor-bound.
// 3-stage single-sync pipeline. grid (4 ntiles, 512 mtiles), 256 threads.
// ---------------------------------------------------------------------------
__global__ void __launch_bounds__(256, 1)
gemm_mma_kernel(const float* __restrict__ v_w) {
    extern __shared__ char smem[];
    const uint32_t sb = smem_u32(smem);
    const int tid  = threadIdx.x;
    const int lane = tid & 31;
    const int warp = tid >> 5;
    const int wm   = warp & 1;        // 0..1: 64-row slice
    const int wn   = warp >> 1;       // 0..3: 64-col slice
    const int m0 = blockIdx.y * 128;
    const int n0 = blockIdx.x * 256;

    float* sbias = (float*)(smem + OFF_SBIAS);
    float* svw   = (float*)(smem + OFF_SVW);
    sbias[tid] = g_bias[n0 + tid];
    svw[tid]   = v_w[n0 + tid];

    // Producer: A rows 0..127 (4/thread), B rows 0..255 (8/thread).
    const int seg = tid & 7;
    const int r0  = tid >> 3;         // 0..31
    const __half* pA[4];
    const __half* pB[8];
    uint32_t soffA[4], soffB[8];
#pragma unroll
    for (int v = 0; v < 4; v++) {
        int r = r0 + v * 32;
        soffA[v] = (uint32_t)r * 128 + (uint32_t)((seg ^ (r & 7)) * 16);
        pA[v] = g_h_hi + (size_t)(m0 + r) * 1024 + seg * 8;
    }
#pragma unroll
    for (int v = 0; v < 8; v++) {
        int r = r0 + v * 32;
        soffB[v] = (uint32_t)r * 128 + (uint32_t)((seg ^ (r & 7)) * 16);
        pB[v] = g_w_hi + (size_t)(n0 + r) * 1024 + seg * 8;
    }

#define ISSUE_CHUNK(BUF) do {                                             \
    uint32_t sbase = sb + (BUF) * STAGE_STRIDE;                           \
    _Pragma("unroll")                                                     \
    for (int v = 0; v < 4; v++) {                                         \
        cp16(sbase + OFF_A + soffA[v], pA[v]);                            \
        pA[v] += 64;                                                      \
    }                                                                     \
    _Pragma("unroll")                                                     \
    for (int v = 0; v < 8; v++) {                                         \
        cp16(sbase + OFF_B + soffB[v], pB[v]);                            \
        pB[v] += 64;                                                      \
    }                                                                     \
    asm volatile("cp.async.commit_group;" ::: "memory");                  \
} while (0)

    const int lrow  = lane & 15;
    const int lhalf = lane >> 4;

    // Hoisted swizzle bases
    int rA[4], r7A[4], rB[4], r7B[4];
#pragma unroll
    for (int mi = 0; mi < 4; mi++) {
        int r = wm * 64 + mi * 16 + lrow;
        rA[mi] = r * 128; r7A[mi] = (r & 7) * 16;
    }
#pragma unroll
    for (int ng = 0; ng < 4; ng++) {
        int r = wn * 64 + ng * 16 + lrow;
        rB[ng] = r * 128; r7B[ng] = (r & 7) * 16;
    }

    float acc[4][8][4] = {};

    // prologue: stages 0 and 1
    ISSUE_CHUNK(0);
    ISSUE_CHUNK(1);

    int buf = 0;
    for (int c = 0; c < 16; c++) {
        if (c < 15) asm volatile("cp.async.wait_group 1;" ::: "memory");
        else        asm volatile("cp.async.wait_group 0;" ::: "memory");
        __syncthreads();          // chunk c visible; buf (c+2)%3 free
        if (c < 14) {
            int nb = buf + 2; if (nb >= 3) nb -= 3;
            ISSUE_CHUNK(nb);
        }
        const uint32_t st = sb + buf * STAGE_STRIDE;

#pragma unroll
        for (int ks = 0; ks < 4; ks++) {
            uint32_t kk = (uint32_t)((ks * 2 + lhalf) * 16);
            uint32_t aF[4][4];
            uint32_t bF[4][4];
#pragma unroll
            for (int mi = 0; mi < 4; mi++) {
                uint32_t off = (uint32_t)rA[mi] + (kk ^ (uint32_t)r7A[mi]);
                LDSM4(aF[mi], st + OFF_A + off);
            }
#pragma unroll
            for (int ng = 0; ng < 4; ng++) {
                uint32_t off = (uint32_t)rB[ng] + (kk ^ (uint32_t)r7B[ng]);
                LDSM4(bF[ng], st + OFF_B + off);
            }
#pragma unroll
            for (int mi = 0; mi < 4; mi++)
#pragma unroll
                for (int nt = 0; nt < 8; nt++) {
                    int ng = nt >> 1, hf = nt & 1;
                    mma16816h(acc[mi][nt], aF[mi], bF[ng][hf], bF[ng][2 + hf]);
                }
        }
        if (++buf >= 3) buf = 0;
    }

    // Epilogue: tanh(acc + bias) dot v_w over this warp's 64 cols.
    const int g = lane >> 2, tig = lane & 3;
#pragma unroll
    for (int mi = 0; mi < 4; mi++)
#pragma unroll
        for (int rg = 0; rg < 2; rg++) {
            float s = 0.f;
#pragma unroll
            for (int nt = 0; nt < 8; nt++) {
                int col = wn * 64 + nt * 8 + tig * 2;
                float p0 = acc[mi][nt][rg * 2 + 0] + sbias[col];
                float p1 = acc[mi][nt][rg * 2 + 1] + sbias[col + 1];
                s = fmaf(tanh_fast(p0), svw[col], s);
                s = fmaf(tanh_fast(p1), svw[col + 1], s);
            }
            s += __shfl_down_sync(0xffffffffu, s, 1, 4);
            s += __shfl_down_sync(0xffffffffu, s, 2, 4);
            if (tig == 0) {
                int row = m0 + wm * 64 + mi * 16 + rg * 8 + g;
                g_spart[(size_t)(blockIdx.x * 4 + wn) * BL + row] = s;
            }
        }
}

// ---------------------------------------------------------------------------
// Fused preprocessing: convert_h (blocks 0..32767), convert_w (32768..33791),
// bias (33792..34815).
// ---------------------------------------------------------------------------
__global__ void __launch_bounds__(256)
prep_kernel(const float* __restrict__ h, const float* __restrict__ ln_w,
            const float* __restrict__ ln_b, const float* __restrict__ vq) {
    int bx = blockIdx.x;
    if (bx < 32768) {
        size_t i = ((size_t)bx * 256 + threadIdx.x) * 8;
        float4 v0 = *reinterpret_cast<const float4*>(h + i);
        float4 v1 = *reinterpret_cast<const float4*>(h + i + 4);
        union { __half2 p[4]; uint4 u; } out;
        out.p[0] = __floats2half2_rn(v0.x, v0.y);
        out.p[1] = __floats2half2_rn(v0.z, v0.w);
        out.p[2] = __floats2half2_rn(v1.x, v1.y);
        out.p[3] = __floats2half2_rn(v1.z, v1.w);
        *reinterpret_cast<uint4*>(g_h_hi + i) = out.u;
    } else if (bx < 33792) {
        size_t e = ((size_t)(bx - 32768) * 256 + threadIdx.x) * 4;
        int n = (int)(e >> 10), k = (int)(e & 1023);
        float4 v = *reinterpret_cast<const float4*>(ln_w + (size_t)n * 2048 + k);
        union { __half2 p[2]; uint64_t u; } out;
        out.p[0] = __floats2half2_rn(v.x, v.y);
        out.p[1] = __floats2half2_rn(v.z, v.w);
        *reinterpret_cast<uint64_t*>(g_w_hi + e) = out.u;
    } else {
        int hh = bx - 33792;
        const float* wrow = ln_w + (size_t)hh * 2048 + 1024;
        float sum = 0.f;
        for (int i = threadIdx.x; i < 1024; i += 256)
            sum = fmaf(wrow[i], vq[i], sum);
        __shared__ float red[256];
        red[threadIdx.x] = sum;
        __syncthreads();
        for (int st = 128; st > 0; st >>= 1) {
            if (threadIdx.x < st) red[threadIdx.x] += red[threadIdx.x + st];
            __syncthreads();
        }
        if (threadIdx.x == 0) g_bias[hh] = ln_b[hh] + red[0];
    }
}

__global__ void softmax_kernel(const int* __restrict__ mask) {
    int b = blockIdx.x;
    __shared__ float red[256];
    float vals[8];
    float mx = -1e30f;
#pragma unroll
    for (int j = 0; j < 8; j++) {
        int idx = b * LLEN + threadIdx.x + j * 256;
        float v = 0.f;
#pragma unroll
        for (int ct = 0; ct < NCTS; ct++)
            v += g_spart[(size_t)ct * BL + idx];
        if (mask[idx] == 0) v -= 10000.f;
        vals[j] = v;
        mx = fmaxf(mx, v);
    }
    red[threadIdx.x] = mx;
    __syncthreads();
    for (int st = 128; st > 0; st >>= 1) {
        if (threadIdx.x < st) red[threadIdx.x] = fmaxf(red[threadIdx.x], red[threadIdx.x + st]);
        __syncthreads();
    }
    mx = red[0];
    __syncthreads();
    float se = 0.f;
#pragma unroll
    for (int j = 0; j < 8; j++) { vals[j] = __expf(vals[j] - mx); se += vals[j]; }
    red[threadIdx.x] = se;
    __syncthreads();
    for (int st = 128; st > 0; st >>= 1) {
        if (threadIdx.x < st) red[threadIdx.x] += red[threadIdx.x + st];
        __syncthreads();
    }
    float inv = 1.f / red[0];
#pragma unroll
    for (int j = 0; j < 8; j++)
        g_a[b * LLEN + threadIdx.x + j * 256] = vals[j] * inv;
}

// wsum over fp16 h (reuses g_h_hi): r[b,c] = sum_l a[b,l] * h[b,l,c].
__global__ void __launch_bounds__(256)
wsum_part_kernel() {
    int b = blockIdx.y, sl = blockIdx.z;
    int c2 = blockIdx.x * 256 + threadIdx.x;       // half2 column index
    int l0 = sl * 256;
    __shared__ float aw[256];
    aw[threadIdx.x] = g_a[b * LLEN + l0 + threadIdx.x];
    __syncthreads();
    const __half2* hp = reinterpret_cast<const __half2*>(g_h_hi) +
                        ((size_t)b * LLEN + l0) * 512 + c2;
    float accx = 0.f, accy = 0.f;
#pragma unroll 8
    for (int l = 0; l < 256; l++) {
        float2 v = __half22float2(hp[(size_t)l * 512]);
        float w = aw[l];
        accx = fmaf(w, v.x, accx);
        accy = fmaf(w, v.y, accy);
    }
    float2* dst = reinterpret_cast<float2*>(&g_rpart[sl][b * 1024 + c2 * 2]);
    *dst = make_float2(accx, accy);
}

__global__ void wsum_reduce_kernel(float* __restrict__ out) {
    int i = blockIdx.x * 256 + threadIdx.x;
    float acc = 0.f;
#pragma unroll
    for (int sl = 0; sl < 8; sl++) acc += g_rpart[sl][i];
    out[i] = acc;
}

// ---------------------------------------------------------------------------
extern "C" void kernel_launch(void* const* d_in, const int* in_sizes, int n_in,
                              void* d_out, int out_size) {
    const float* h    = (const float*)d_in[0];
    const int*   mask = (const int*)d_in[1];
    const float* ln_w = (const float*)d_in[2];
    const float* ln_b = (const float*)d_in[3];
    const float* v_w  = (const float*)d_in[4];
    const float* vq   = (const float*)d_in[5];
    float* out = (float*)d_out;

    cudaFuncSetAttribute(gemm_mma_kernel,
                         cudaFuncAttributeMaxDynamicSharedMemorySize, SMEM_BYTES);

    prep_kernel<<<34816, 256>>>(h, ln_w, ln_b, vq);

    gemm_mma_kernel<<<dim3(4, 512), 256, SMEM_BYTES>>>(v_w);

    softmax_kernel<<<BATCH, 256>>>(mask);

    wsum_part_kernel<<<dim3(2, BATCH, 8), 256>>>();
    wsum_reduce_kernel<<<128, 256>>>(out);
}

// round 13
// speedup vs baseline: 1.2410x; 1.2410x over previous
#include <cuda_runtime.h>
#include <cuda_fp16.h>
#include <cstdint>

#define BATCH 32
#define LLEN  2048
#define BL    (BATCH * LLEN)      // 65536
#define NCTS  16                  // 8 ntiles x 2 warp halves
#define NSL   16                  // wsum L-slices

// ------------------------------- device scratch ----------------------------
__device__ __align__(16) __half g_h_hi[67108864];   // [BL][1024] fp16(h)
__device__ __align__(16) __half g_w_hi[1048576];    // [1024 N][1024 K] fp16(W)
__device__ float g_bias[1024];
__device__ float g_spart[NCTS * BL];
__device__ float g_a[BL];
__device__ float g_rpart[NSL][BATCH * 1024];

// ------------------------------- PTX helpers -------------------------------
__device__ __forceinline__ uint32_t smem_u32(const void* p) {
    uint32_t a;
    asm("{ .reg .u64 t; cvta.to.shared.u64 t, %1; cvt.u32.u64 %0, t; }" : "=r"(a) : "l"(p));
    return a;
}
__device__ __forceinline__ void cp16(uint32_t dst, const void* src) {
    asm volatile("cp.async.cg.shared.global [%0], [%1], 16;" :: "r"(dst), "l"(src));
}
#define LDSM4(r, addr) \
    asm volatile("ldmatrix.sync.aligned.m8n8.x4.shared.b16 {%0,%1,%2,%3}, [%4];" \
        : "=r"((r)[0]), "=r"((r)[1]), "=r"((r)[2]), "=r"((r)[3]) : "r"(addr))

__device__ __forceinline__ void mma16816h(float* d, const uint32_t* a,
                                          uint32_t b0, uint32_t b1) {
    asm volatile("mma.sync.aligned.m16n8k16.row.col.f32.f16.f16.f32 "
        "{%0,%1,%2,%3}, {%4,%5,%6,%7}, {%8,%9}, {%0,%1,%2,%3};"
        : "+f"(d[0]), "+f"(d[1]), "+f"(d[2]), "+f"(d[3])
        : "r"(a[0]), "r"(a[1]), "r"(a[2]), "r"(a[3]), "r"(b0), "r"(b1));
}

__device__ __forceinline__ float tanh_fast(float x) {
    float e = __expf(2.f * x);
    return 1.f - 2.f / (e + 1.f);
}

// ------------------------------- GEMM constants ----------------------------
// Per stage (32 KB): A 16K | B 16K (128 rows x 128 B, SW128). 3 stages = 96 KB
// + 1 KB params -> 2 CTAs/SM. PROVEN OPTIMUM: 361 us / tensor 62.5%.
#define STAGE_STRIDE 32768
#define OFF_A 0
#define OFF_B 16384
#define OFF_SBIAS 98304
#define OFF_SVW   98816
#define SMEM_BYTES 99328

// ---------------------------------------------------------------------------
// HMMA GEMM: pre[128 rows, 128 cols] over K=1024, fp16 x fp16 -> fp32.
// 8 warps (4 M x 2 N) of 32x64 tiles; 3-stage pipeline, one sync per chunk,
// 2 CTAs/SM. grid (8 ntiles, 512 mtiles), 256 threads. (Round-11 verified.)
// ---------------------------------------------------------------------------
__global__ void __launch_bounds__(256, 2)
gemm_mma_kernel(const float* __restrict__ v_w) {
    extern __shared__ char smem[];
    const uint32_t sb = smem_u32(smem);
    const int tid  = threadIdx.x;
    const int lane = tid & 31;
    const int warp = tid >> 5;
    const int wm   = warp & 3;        // 0..3: 32-row slice
    const int wn   = warp >> 2;       // 0..1: 64-col slice
    const int m0 = blockIdx.y * 128;
    const int n0 = blockIdx.x * 128;

    float* sbias = (float*)(smem + OFF_SBIAS);
    float* svw   = (float*)(smem + OFF_SVW);
    if (tid < 128) {
        sbias[tid] = g_bias[n0 + tid];
        svw[tid]   = v_w[n0 + tid];
    }

    // Producer state: hoisted pointers, advanced +64 halves per chunk.
    const int seg = tid & 7;
    const int r0  = tid >> 3;
    const __half* pA[4];
    const __half* pB[4];
    uint32_t soff[4];
#pragma unroll
    for (int v = 0; v < 4; v++) {
        int r = r0 + v * 32;
        soff[v] = (uint32_t)r * 128 + (uint32_t)((seg ^ (r & 7)) * 16);
        pA[v] = g_h_hi + (size_t)(m0 + r) * 1024 + seg * 8;
        pB[v] = g_w_hi + (size_t)(n0 + r) * 1024 + seg * 8;
    }

#define ISSUE_CHUNK(BUF) do {                                             \
    uint32_t sbase = sb + (BUF) * STAGE_STRIDE;                           \
    _Pragma("unroll")                                                     \
    for (int v = 0; v < 4; v++) {                                         \
        cp16(sbase + OFF_A + soff[v], pA[v]);                             \
        cp16(sbase + OFF_B + soff[v], pB[v]);                             \
        pA[v] += 64; pB[v] += 64;                                         \
    }                                                                     \
    asm volatile("cp.async.commit_group;" ::: "memory");                  \
} while (0)

    const int lrow  = lane & 15;
    const int lhalf = lane >> 4;

    // Hoisted swizzle bases: offset(ks) = rX + (((ks*2+lhalf)<<4) ^ r7X)
    int rA[2], r7A[2], rB[4], r7B[4];
#pragma unroll
    for (int mi = 0; mi < 2; mi++) {
        int r = wm * 32 + mi * 16 + lrow;
        rA[mi] = r * 128; r7A[mi] = (r & 7) * 16;
    }
#pragma unroll
    for (int ng = 0; ng < 4; ng++) {
        int r = wn * 64 + ng * 16 + lrow;
        rB[ng] = r * 128; r7B[ng] = (r & 7) * 16;
    }

    float acc[2][8][4] = {};

    // prologue: stages 0 and 1
    ISSUE_CHUNK(0);
    ISSUE_CHUNK(1);

    int buf = 0;
    for (int c = 0; c < 16; c++) {
        if (c < 15) asm volatile("cp.async.wait_group 1;" ::: "memory");
        else        asm volatile("cp.async.wait_group 0;" ::: "memory");
        __syncthreads();          // chunk c visible; buf (c+2)%3 free
        if (c < 14) {
            int nb = buf + 2; if (nb >= 3) nb -= 3;
            ISSUE_CHUNK(nb);
        }
        const uint32_t st = sb + buf * STAGE_STRIDE;

#pragma unroll
        for (int ks = 0; ks < 4; ks++) {
            uint32_t kk = (uint32_t)((ks * 2 + lhalf) * 16);
            uint32_t aF[2][4];
            uint32_t bF[4][4];
#pragma unroll
            for (int mi = 0; mi < 2; mi++) {
                uint32_t off = (uint32_t)rA[mi] + (kk ^ (uint32_t)r7A[mi]);
                LDSM4(aF[mi], st + OFF_A + off);
            }
#pragma unroll
            for (int ng = 0; ng < 4; ng++) {
                uint32_t off = (uint32_t)rB[ng] + (kk ^ (uint32_t)r7B[ng]);
                LDSM4(bF[ng], st + OFF_B + off);
            }
#pragma unroll
            for (int mi = 0; mi < 2; mi++)
#pragma unroll
                for (int nt = 0; nt < 8; nt++) {
                    int ng = nt >> 1, hf = nt & 1;
                    mma16816h(acc[mi][nt], aF[mi], bF[ng][hf], bF[ng][2 + hf]);
                }
        }
        if (++buf >= 3) buf = 0;
    }

    // Epilogue: tanh(acc + bias) dot v_w, reduced over this warp's 64 cols.
    const int g = lane >> 2, tig = lane & 3;
#pragma unroll
    for (int mi = 0; mi < 2; mi++)
#pragma unroll
        for (int rg = 0; rg < 2; rg++) {
            float s = 0.f;
#pragma unroll
            for (int nt = 0; nt < 8; nt++) {
                int col = wn * 64 + nt * 8 + tig * 2;
                float p0 = acc[mi][nt][rg * 2 + 0] + sbias[col];
                float p1 = acc[mi][nt][rg * 2 + 1] + sbias[col + 1];
                s = fmaf(tanh_fast(p0), svw[col], s);
                s = fmaf(tanh_fast(p1), svw[col + 1], s);
            }
            s += __shfl_down_sync(0xffffffffu, s, 1, 4);
            s += __shfl_down_sync(0xffffffffu, s, 2, 4);
            if (tig == 0) {
                int row = m0 + wm * 32 + mi * 16 + rg * 8 + g;
                g_spart[(size_t)(blockIdx.x * 2 + wn) * BL + row] = s;
            }
        }
}

// ---------------------------------------------------------------------------
// Fused preprocessing: convert_h (blocks 0..32767), convert_w (32768..33791),
// bias (33792..34815).
// ---------------------------------------------------------------------------
__global__ void __launch_bounds__(256)
prep_kernel(const float* __restrict__ h, const float* __restrict__ ln_w,
            const float* __restrict__ ln_b, const float* __restrict__ vq) {
    int bx = blockIdx.x;
    if (bx < 32768) {
        size_t i = ((size_t)bx * 256 + threadIdx.x) * 8;
        float4 v0 = *reinterpret_cast<const float4*>(h + i);
        float4 v1 = *reinterpret_cast<const float4*>(h + i + 4);
        union { __half2 p[4]; uint4 u; } out;
        out.p[0] = __floats2half2_rn(v0.x, v0.y);
        out.p[1] = __floats2half2_rn(v0.z, v0.w);
        out.p[2] = __floats2half2_rn(v1.x, v1.y);
        out.p[3] = __floats2half2_rn(v1.z, v1.w);
        *reinterpret_cast<uint4*>(g_h_hi + i) = out.u;
    } else if (bx < 33792) {
        size_t e = ((size_t)(bx - 32768) * 256 + threadIdx.x) * 4;
        int n = (int)(e >> 10), k = (int)(e & 1023);
        float4 v = *reinterpret_cast<const float4*>(ln_w + (size_t)n * 2048 + k);
        union { __half2 p[2]; uint64_t u; } out;
        out.p[0] = __floats2half2_rn(v.x, v.y);
        out.p[1] = __floats2half2_rn(v.z, v.w);
        *reinterpret_cast<uint64_t*>(g_w_hi + e) = out.u;
    } else {
        int hh = bx - 33792;
        const float* wrow = ln_w + (size_t)hh * 2048 + 1024;
        float sum = 0.f;
        for (int i = threadIdx.x; i < 1024; i += 256)
            sum = fmaf(wrow[i], vq[i], sum);
        __shared__ float red[256];
        red[threadIdx.x] = sum;
        __syncthreads();
        for (int st = 128; st > 0; st >>= 1) {
            if (threadIdx.x < st) red[threadIdx.x] += red[threadIdx.x + st];
            __syncthreads();
        }
        if (threadIdx.x == 0) g_bias[hh] = ln_b[hh] + red[0];
    }
}

__global__ void softmax_kernel(const int* __restrict__ mask) {
    int b = blockIdx.x;
    __shared__ float red[256];
    float vals[8];
    float mx = -1e30f;
#pragma unroll
    for (int j = 0; j < 8; j++) {
        int idx = b * LLEN + threadIdx.x + j * 256;
        float v = 0.f;
#pragma unroll
        for (int ct = 0; ct < NCTS; ct++)
            v += g_spart[(size_t)ct * BL + idx];
        if (mask[idx] == 0) v -= 10000.f;
        vals[j] = v;
        mx = fmaxf(mx, v);
    }
    red[threadIdx.x] = mx;
    __syncthreads();
    for (int st = 128; st > 0; st >>= 1) {
        if (threadIdx.x < st) red[threadIdx.x] = fmaxf(red[threadIdx.x], red[threadIdx.x + st]);
        __syncthreads();
    }
    mx = red[0];
    __syncthreads();
    float se = 0.f;
#pragma unroll
    for (int j = 0; j < 8; j++) { vals[j] = __expf(vals[j] - mx); se += vals[j]; }
    red[threadIdx.x] = se;
    __syncthreads();
    for (int st = 128; st > 0; st >>= 1) {
        if (threadIdx.x < st) red[threadIdx.x] += red[threadIdx.x + st];
        __syncthreads();
    }
    float inv = 1.f / red[0];
#pragma unroll
    for (int j = 0; j < 8; j++)
        g_a[b * LLEN + threadIdx.x + j * 256] = vals[j] * inv;
}

// wsum over fp16 h (reuses g_h_hi): r[b,c] = sum_l a[b,l] * h[b,l,c].
// 16 L-slices of 128 rows for higher block-level parallelism (1024 blocks).
__global__ void __launch_bounds__(256)
wsum_part_kernel() {
    int b = blockIdx.y, sl = blockIdx.z;
    int c2 = blockIdx.x * 256 + threadIdx.x;       // half2 column index
    int l0 = sl * 128;
    __shared__ float aw[128];
    if (threadIdx.x < 128)
        aw[threadIdx.x] = g_a[b * LLEN + l0 + threadIdx.x];
    __syncthreads();
    const __half2* hp = reinterpret_cast<const __half2*>(g_h_hi) +
                        ((size_t)b * LLEN + l0) * 512 + c2;
    float accx = 0.f, accy = 0.f;
#pragma unroll 8
    for (int l = 0; l < 128; l++) {
        float2 v = __half22float2(hp[(size_t)l * 512]);
        float w = aw[l];
        accx = fmaf(w, v.x, accx);
        accy = fmaf(w, v.y, accy);
    }
    float2* dst = reinterpret_cast<float2*>(&g_rpart[sl][b * 1024 + c2 * 2]);
    *dst = make_float2(accx, accy);
}

__global__ void wsum_reduce_kernel(float* __restrict__ out) {
    int i = blockIdx.x * 256 + threadIdx.x;
    float acc = 0.f;
#pragma unroll
    for (int sl = 0; sl < NSL; sl++) acc += g_rpart[sl][i];
    out[i] = acc;
}

// ---------------------------------------------------------------------------
extern "C" void kernel_launch(void* const* d_in, const int* in_sizes, int n_in,
                              void* d_out, int out_size) {
    const float* h    = (const float*)d_in[0];
    const int*   mask = (const int*)d_in[1];
    const float* ln_w = (const float*)d_in[2];
    const float* ln_b = (const float*)d_in[3];
    const float* v_w  = (const float*)d_in[4];
    const float* vq   = (const float*)d_in[5];
    float* out = (float*)d_out;

    cudaFuncSetAttribute(gemm_mma_kernel,
                         cudaFuncAttributeMaxDynamicSharedMemorySize, SMEM_BYTES);

    prep_kernel<<<34816, 256>>>(h, ln_w, ln_b, vq);

    gemm_mma_kernel<<<dim3(8, 512), 256, SMEM_BYTES>>>(v_w);

    softmax_kernel<<<BATCH, 256>>>(mask);

    wsum_part_kernel<<<dim3(2, BATCH, NSL), 256>>>();
    wsum_reduce_kernel<<<128, 256>>>(out);
}